// round 12
// baseline (speedup 1.0000x reference)
#include <cuda_runtime.h>
#include <cuda_bf16.h>
#include <mma.h>
#include <cstdint>

using namespace nvcuda;

// out[b,d,h,w] = (1/64) * sum_c left[b,c,h,w]*right[b,c,h,w-d], 0 for w<d
// B=8, C=64, H=160, W=320, D=48.
// wmma bf16 3-term-split banded Gram GEMM, CTA = (b, h, W-half of 160).

#define HH  160
#define WW  320
#define DDn 48
#define HW  (HH * WW)
#define NT  320            // 10 warps, 1 i-tile (16 w) each
#define MW  160            // w-extent per CTA

#define LLD 168            // left stage row stride (bf16 elems), 336 B (16B mult)
#define RLD 264            // right stage row stride, 528 B (16B mult)
#define RW  208            // right stage valid width: 48 pad + 160
#define SLD 68             // scratch row stride (fp32), 272 B (16B mult)

// smem byte offsets
#define SLHI 0
#define SLLO (SLHI + 16 * LLD * 2)       // 5376
#define SRHI (SLLO + 16 * LLD * 2)       // 10752
#define SRLO (SRHI + 16 * RLD * 2)       // 19200
#define SCR  (SRLO + 16 * RLD * 2)       // 27648
#define SMEM_SZ (SCR + 10 * 16 * SLD * 4)  // 27648 + 43520 = 71168

__global__ __launch_bounds__(NT, 2)
void corvol_wmma(const float* __restrict__ left,
                 const float* __restrict__ right,
                 float* __restrict__ out)
{
    extern __shared__ char sm[];
    __nv_bfloat16* sLhi = (__nv_bfloat16*)(sm + SLHI);
    __nv_bfloat16* sLlo = (__nv_bfloat16*)(sm + SLLO);
    __nv_bfloat16* sRhi = (__nv_bfloat16*)(sm + SRHI);
    __nv_bfloat16* sRlo = (__nv_bfloat16*)(sm + SRLO);

    const int bid  = blockIdx.x;
    const int half = bid & 1;
    const int bh   = bid >> 1;
    const int b    = bh / HH;
    const int h    = bh % HH;
    const int h0   = half * MW;              // global w offset of this CTA
    const int tid  = threadIdx.x;
    const int wid  = tid >> 5;
    const int lid  = tid & 31;

    const float* lbase = left  + ((size_t)b * 64 * HH + h) * WW;
    const float* rbase = right + ((size_t)b * 64 * HH + h) * WW;

    // Zero the 48 left-pad columns of the right stage once.
    // (h0==0: never overwritten -> stays zero, masks w<d. h0==160: rewritten each chunk.)
    for (int i = tid; i < 16 * 48; i += NT) {
        const int r = i / 48, c = i % 48;
        sRhi[r * RLD + c] = __float2bfloat16(0.f);
        sRlo[r * RLD + c] = __float2bfloat16(0.f);
    }

    wmma::fragment<wmma::accumulator, 16, 16, 16, float> acc[4];
    #pragma unroll
    for (int j = 0; j < 4; j++) wmma::fill_fragment(acc[j], 0.0f);

    for (int kc = 0; kc < 4; kc++) {
        __syncthreads();   // previous chunk's compute done before restaging

        // Stage left: 16 rows x 160 cols -> hi/lo bf16 (8 elems/thread, coalesced)
        #pragma unroll
        for (int p = 0; p < 8; p++) {
            const int idx = tid + p * NT;
            const int r = idx / MW, c = idx % MW;
            const float x = lbase[(size_t)(16 * kc + r) * HW + h0 + c];
            const __nv_bfloat16 hi = __float2bfloat16(x);
            const __nv_bfloat16 lo = __float2bfloat16(x - __bfloat162float(hi));
            sLhi[r * LLD + c] = hi;
            sLlo[r * LLD + c] = lo;
        }
        // Stage right window: 16 rows x 208 cols (w' = h0-48+c), guard w'>=0
        #pragma unroll
        for (int p = 0; p < 11; p++) {
            const int idx = tid + p * NT;
            if (idx < 16 * RW) {
                const int r = idx / RW, c = idx % RW;
                const int wp = h0 - 48 + c;
                if (wp >= 0) {
                    const float x = rbase[(size_t)(16 * kc + r) * HW + wp];
                    const __nv_bfloat16 hi = __float2bfloat16(x);
                    const __nv_bfloat16 lo = __float2bfloat16(x - __bfloat162float(hi));
                    sRhi[r * RLD + c] = hi;
                    sRlo[r * RLD + c] = lo;
                }
            }
        }
        __syncthreads();

        // A (col_major): element (i,k) = sLhi[k*LLD + wid*16 + i]
        wmma::fragment<wmma::matrix_a, 16, 16, 16, __nv_bfloat16, wmma::col_major> ahi, alo;
        wmma::load_matrix_sync(ahi, sLhi + wid * 16, LLD);
        wmma::load_matrix_sync(alo, sLlo + wid * 16, LLD);

        #pragma unroll
        for (int j = 0; j < 4; j++) {
            // B (row_major): element (k,n) = sRhi[k*RLD + wid*16 + 16j + n]
            // covers w' = (h0 + wid*16) - 48 + 16j + n
            wmma::fragment<wmma::matrix_b, 16, 16, 16, __nv_bfloat16, wmma::row_major> bhi, blo;
            wmma::load_matrix_sync(bhi, sRhi + wid * 16 + 16 * j, RLD);
            wmma::load_matrix_sync(blo, sRlo + wid * 16 + 16 * j, RLD);
            wmma::mma_sync(acc[j], ahi, bhi, acc[j]);
            wmma::mma_sync(acc[j], ahi, blo, acc[j]);
            wmma::mma_sync(acc[j], alo, bhi, acc[j]);
        }
    }

    // Band extraction: D[i][w'] at scr[i][w' - (i0g-48)]; out[d][w] = D[i][w-d]/64
    float* scr = (float*)(sm + SCR) + wid * 16 * SLD;
    #pragma unroll
    for (int j = 0; j < 4; j++)
        wmma::store_matrix_sync(scr + 16 * j, acc[j], SLD, wmma::mem_row_major);
    __syncwarp();

    {
        const int i    = lid & 15;           // row within i-tile
        const int dpar = lid >> 4;           // d parity
        const int wg   = h0 + wid * 16 + i;  // global w
        float* ob = out + ((size_t)b * DDn * HH + h) * WW + wg;
        #pragma unroll
        for (int dd = 0; dd < 24; dd++) {
            const int d = 2 * dd + dpar;
            ob[(size_t)d * HW] = scr[i * SLD + (i + 48 - d)] * 0.015625f;
        }
    }
}

extern "C" void kernel_launch(void* const* d_in, const int* in_sizes, int n_in,
                              void* d_out, int out_size)
{
    cudaFuncSetAttribute(corvol_wmma, cudaFuncAttributeMaxDynamicSharedMemorySize, SMEM_SZ);
    corvol_wmma<<<8 * HH * 2, NT, SMEM_SZ>>>((const float*)d_in[0],
                                             (const float*)d_in[1],
                                             (float*)d_out);
}

// round 13
// speedup vs baseline: 2.0499x; 2.0499x over previous
#include <cuda_runtime.h>
#include <cuda_bf16.h>
#include <mma.h>
#include <cstdint>

using namespace nvcuda;

// out[b,d,h,w] = (1/64) * sum_c left[b,c,h,w]*right[b,c,h,w-d], 0 for w<d
// B=8, C=64, H=160, W=320, D=48.
// wmma bf16 3-term-split banded Gram GEMM + cp.async double-buffered staging.

#define HH  160
#define WW  320
#define DDn 48
#define HW  (HH * WW)
#define NT  320            // 10 warps, 1 i-tile (16 w) each
#define MW  160            // w-extent per CTA

#define F32L_LD 164        // fp32 left stage row stride (floats)
#define F32R_LD 212        // fp32 right stage row stride (floats)
#define RW      208        // right window width: 48 pad + 160
#define LLD     168        // bf16 left tile row stride
#define RLD     264        // bf16 right tile row stride
#define SLD     68         // fp32 scratch row stride

// smem byte offsets
#define F32L0   0
#define F32L1   10496      // 16*164*4
#define F32R0   20992
#define F32R1   34560      // +16*212*4
#define SLHI    48128
#define SLLO    53504      // +16*168*2
#define SRHI    58880
#define SRLO    67328      // +16*264*2
#define SMEM_SZ 75776
#define SCR     0          // scratch overlays fp32 stages (dead by then): 43520 <= 48128

static __device__ __forceinline__ uint32_t s2u(const void* p) {
    uint32_t a;
    asm("{ .reg .u64 t; cvta.to.shared.u64 t, %1; cvt.u32.u64 %0, t; }" : "=r"(a) : "l"(p));
    return a;
}
static __device__ __forceinline__ void cpasync16(void* dst, const void* src) {
    asm volatile("cp.async.cg.shared.global [%0], [%1], 16;"
                 :: "r"(s2u(dst)), "l"(src) : "memory");
}

__global__ __launch_bounds__(NT, 2)
void corvol_wmma(const float* __restrict__ left,
                 const float* __restrict__ right,
                 float* __restrict__ out)
{
    extern __shared__ char sm[];
    __nv_bfloat16* sLhi = (__nv_bfloat16*)(sm + SLHI);
    __nv_bfloat16* sLlo = (__nv_bfloat16*)(sm + SLLO);
    __nv_bfloat16* sRhi = (__nv_bfloat16*)(sm + SRHI);
    __nv_bfloat16* sRlo = (__nv_bfloat16*)(sm + SRLO);

    const int bid  = blockIdx.x;
    const int half = bid & 1;
    const int bh   = bid >> 1;
    const int b    = bh / HH;
    const int h    = bh % HH;
    const int h0   = half * MW;
    const int tid  = threadIdx.x;
    const int wid  = tid >> 5;
    const int lid  = tid & 31;

    const float* lbase = left  + ((size_t)b * 64 * HH + h) * WW;
    const float* rbase = right + ((size_t)b * 64 * HH + h) * WW;

    // h0==0: zero right-stage cols [0,48) in BOTH buffers once; those columns are
    // never cp.async-overwritten (w' < 0), so they stay zero -> w<d mask is free.
    if (h0 == 0) {
        for (int i = tid; i < 2 * 16 * 12; i += NT) {       // 12 float4 per row
            const int bf = i / (16 * 12);
            const int r  = (i / 12) % 16;
            const int c  = (i % 12) * 4;
            float* st = (float*)(sm + (bf ? F32R1 : F32R0));
            *(float4*)&st[r * F32R_LD + c] = make_float4(0.f, 0.f, 0.f, 0.f);
        }
    }
    __syncthreads();

    // stage chunk kc's raw fp32 into buffer kc&1
    auto issue_stage = [&](int kc) {
        const int bf = kc & 1;
        float* fL = (float*)(sm + (bf ? F32L1 : F32L0));
        float* fR = (float*)(sm + (bf ? F32R1 : F32R0));
        // left: 16 rows x 160 cols = 640 float4 (2 per thread)
        #pragma unroll
        for (int p = 0; p < 2; p++) {
            const int idx = tid + p * NT;
            const int r = idx >> 5, c = (idx & 31) * 4 + ((idx >> 5) & 0) ;
            const int rr = idx / 40, cc = (idx % 40) * 4;
            (void)r; (void)c;
            cpasync16(&fL[rr * F32L_LD + cc],
                      lbase + (size_t)(16 * kc + rr) * HW + h0 + cc);
        }
        // right: 16 rows x 52 float4 = 832 (2.6 per thread)
        #pragma unroll
        for (int p = 0; p < 3; p++) {
            const int idx = tid + p * NT;
            if (idx < 16 * 52) {
                const int rr = idx / 52, cc = (idx % 52) * 4;
                const int wp = h0 - 48 + cc;
                if (wp >= 0)
                    cpasync16(&fR[rr * F32R_LD + cc],
                              rbase + (size_t)(16 * kc + rr) * HW + wp);
            }
        }
        asm volatile("cp.async.commit_group;" ::: "memory");
    };

    issue_stage(0);

    wmma::fragment<wmma::accumulator, 16, 16, 16, float> acc[4];
    #pragma unroll
    for (int j = 0; j < 4; j++) wmma::fill_fragment(acc[j], 0.0f);

    for (int kc = 0; kc < 4; kc++) {
        const int bf = kc & 1;
        if (kc < 3) {
            issue_stage(kc + 1);
            asm volatile("cp.async.wait_group 1;" ::: "memory");
        } else {
            asm volatile("cp.async.wait_group 0;" ::: "memory");
        }
        __syncthreads();   // chunk kc fp32 visible; also protects bf16 tiles from prev MMA readers

        const float* fL = (const float*)(sm + (bf ? F32L1 : F32L0));
        const float* fR = (const float*)(sm + (bf ? F32R1 : F32R0));

        // convert left: 16 rows x 80 pairs = 1280 (4 per thread)
        #pragma unroll
        for (int p = 0; p < 4; p++) {
            const int idx = tid + p * NT;
            const int r = idx / 80, c = (idx % 80) * 2;
            const float2 x = *(const float2*)&fL[r * F32L_LD + c];
            const __nv_bfloat162 H = __floats2bfloat162_rn(x.x, x.y);
            const __nv_bfloat162 L = __floats2bfloat162_rn(
                x.x - __bfloat162float(H.x), x.y - __bfloat162float(H.y));
            *(__nv_bfloat162*)&sLhi[r * LLD + c] = H;
            *(__nv_bfloat162*)&sLlo[r * LLD + c] = L;
        }
        // convert right: 16 rows x 104 pairs = 1664 (<=6 per thread)
        #pragma unroll
        for (int p = 0; p < 6; p++) {
            const int idx = tid + p * NT;
            if (idx < 16 * 104) {
                const int r = idx / 104, c = (idx % 104) * 2;
                const float2 x = *(const float2*)&fR[r * F32R_LD + c];
                const __nv_bfloat162 H = __floats2bfloat162_rn(x.x, x.y);
                const __nv_bfloat162 L = __floats2bfloat162_rn(
                    x.x - __bfloat162float(H.x), x.y - __bfloat162float(H.y));
                *(__nv_bfloat162*)&sRhi[r * RLD + c] = H;
                *(__nv_bfloat162*)&sRlo[r * RLD + c] = L;
            }
        }
        __syncthreads();

        wmma::fragment<wmma::matrix_a, 16, 16, 16, __nv_bfloat16, wmma::col_major> ahi, alo;
        wmma::load_matrix_sync(ahi, sLhi + wid * 16, LLD);
        wmma::load_matrix_sync(alo, sLlo + wid * 16, LLD);

        #pragma unroll
        for (int j = 0; j < 4; j++) {
            wmma::fragment<wmma::matrix_b, 16, 16, 16, __nv_bfloat16, wmma::row_major> bhi, blo;
            wmma::load_matrix_sync(bhi, sRhi + wid * 16 + 16 * j, RLD);
            wmma::load_matrix_sync(blo, sRlo + wid * 16 + 16 * j, RLD);
            wmma::mma_sync(acc[j], ahi, bhi, acc[j]);
            wmma::mma_sync(acc[j], ahi, blo, acc[j]);
            wmma::mma_sync(acc[j], alo, bhi, acc[j]);
        }
    }

    // Band extraction. Scratch overlays the (now dead) fp32 stages; the bf16 tiles
    // other warps may still be MMA-reading are NOT overlaid, so no sync needed.
    float* scr = (float*)(sm + SCR) + wid * 16 * SLD;
    #pragma unroll
    for (int j = 0; j < 4; j++)
        wmma::store_matrix_sync(scr + 16 * j, acc[j], SLD, wmma::mem_row_major);
    __syncwarp();

    {
        const int i    = lid & 15;
        const int dpar = lid >> 4;
        const int wg   = h0 + wid * 16 + i;
        float* ob = out + ((size_t)b * DDn * HH + h) * WW + wg;
        #pragma unroll
        for (int dd = 0; dd < 24; dd++) {
            const int d = 2 * dd + dpar;
            ob[(size_t)d * HW] = scr[i * SLD + (i + 48 - d)] * 0.015625f;
        }
    }
}

extern "C" void kernel_launch(void* const* d_in, const int* in_sizes, int n_in,
                              void* d_out, int out_size)
{
    cudaFuncSetAttribute(corvol_wmma, cudaFuncAttributeMaxDynamicSharedMemorySize, SMEM_SZ);
    corvol_wmma<<<8 * HH * 2, NT, SMEM_SZ>>>((const float*)d_in[0],
                                             (const float*)d_in[1],
                                             (float*)d_out);
}

// round 14
// speedup vs baseline: 2.1288x; 1.0385x over previous
#include <cuda_runtime.h>
#include <mma.h>
#include <cstdint>

using namespace nvcuda;

// out[b,d,h,w] = (1/64) * sum_c left[b,c,h,w]*right[b,c,h,w-d], 0 for w<d
// B=8, C=64, H=160, W=320, D=48.
// tf32 single-pass banded Gram GEMM, wmma m16n16k8, fragments loaded directly
// from fp32 cp.async stages (no convert phase, no bf16 tiles). 3-deep pipeline.

#define HH  160
#define WW  320
#define DDn 48
#define HW  (HH * WW)
#define NT  320            // 10 warps, 1 i-tile (16 w) each
#define MW  160            // w-extent per CTA

#define LLD 168            // fp32 left stage row stride (floats), mult of 8
#define RLD 216            // fp32 right stage row stride (floats), mult of 8
#define SLD 68             // fp32 scratch row stride

// smem byte offsets: 3 buffers each of left (16x168 fp32 = 10752 B) and
// right (16x216 fp32 = 13824 B)
#define SLB(i) ((i) * 10752)
#define SRB(i) (32256 + (i) * 13824)
#define SMEM_SZ 73728
#define SCR 0              // epilogue scratch overlays stages (43520 <= 73728)

static __device__ __forceinline__ uint32_t s2u(const void* p) {
    uint32_t a;
    asm("{ .reg .u64 t; cvta.to.shared.u64 t, %1; cvt.u32.u64 %0, t; }" : "=r"(a) : "l"(p));
    return a;
}
static __device__ __forceinline__ void cpasync16(void* dst, const void* src) {
    asm volatile("cp.async.cg.shared.global [%0], [%1], 16;"
                 :: "r"(s2u(dst)), "l"(src) : "memory");
}

__global__ __launch_bounds__(NT, 2)
void corvol_tf32(const float* __restrict__ left,
                 const float* __restrict__ right,
                 float* __restrict__ out)
{
    extern __shared__ char sm[];

    const int bid  = blockIdx.x;
    const int half = bid & 1;
    const int bh   = bid >> 1;
    const int b    = bh / HH;
    const int h    = bh % HH;
    const int h0   = half * MW;
    const int tid  = threadIdx.x;
    const int wid  = tid >> 5;
    const int lid  = tid & 31;

    const float* lbase = left  + ((size_t)b * 64 * HH + h) * WW;
    const float* rbase = right + ((size_t)b * 64 * HH + h) * WW;

    // h0==0: zero right-stage cols [0,48) in ALL 3 buffers once; those columns
    // are never cp.async-overwritten (w' < 0) -> stays zero -> w<d mask free.
    if (h0 == 0) {
        for (int i = tid; i < 3 * 16 * 12; i += NT) {     // 12 float4 per row
            const int bf = i / (16 * 12);
            const int r  = (i / 12) % 16;
            const int c  = (i % 12) * 4;
            float* st = (float*)(sm + SRB(bf));
            *(float4*)&st[r * RLD + c] = make_float4(0.f, 0.f, 0.f, 0.f);
        }
    }
    __syncthreads();

    // stage chunk kc's fp32 into buffer kc % 3
    auto issue_stage = [&](int kc) {
        const int bf = kc % 3;
        float* fL = (float*)(sm + SLB(bf));
        float* fR = (float*)(sm + SRB(bf));
        // left: 16 rows x 40 float4 = 640 (2 per thread)
        #pragma unroll
        for (int p = 0; p < 2; p++) {
            const int idx = tid + p * NT;
            const int rr = idx / 40, cc = (idx % 40) * 4;
            cpasync16(&fL[rr * LLD + cc],
                      lbase + (size_t)(16 * kc + rr) * HW + h0 + cc);
        }
        // right: 16 rows x 52 float4 = 832 (<=3 per thread)
        #pragma unroll
        for (int p = 0; p < 3; p++) {
            const int idx = tid + p * NT;
            if (idx < 16 * 52) {
                const int rr = idx / 52, cc = (idx % 52) * 4;
                const int wp = h0 - 48 + cc;
                if (wp >= 0)
                    cpasync16(&fR[rr * RLD + cc],
                              rbase + (size_t)(16 * kc + rr) * HW + wp);
            }
        }
        asm volatile("cp.async.commit_group;" ::: "memory");
    };

    issue_stage(0);
    issue_stage(1);

    wmma::fragment<wmma::accumulator, 16, 16, 8, float> acc[4];
    #pragma unroll
    for (int j = 0; j < 4; j++) wmma::fill_fragment(acc[j], 0.0f);

    for (int kc = 0; kc < 4; kc++) {
        const int bf = kc % 3;
        if (kc < 2) {
            asm volatile("cp.async.wait_group 1;" ::: "memory");
        } else {
            asm volatile("cp.async.wait_group 0;" ::: "memory");
        }
        __syncthreads();   // chunk kc visible to all; all warps done with iter kc-1

        // Issue kc+2 into buffer (kc+2)%3 == (kc-1)%3; safe: the sync above
        // guarantees every warp finished MMA-reading that buffer (iter kc-1).
        if (kc + 2 < 4) issue_stage(kc + 2);

        const float* fL = (const float*)(sm + SLB(bf));
        const float* fR = (const float*)(sm + SRB(bf));

        // A (16x8, col_major): (i,k) at fL[k*LLD + wid*16 + i]; two k-halves
        wmma::fragment<wmma::matrix_a, 16, 16, 8, wmma::precision::tf32,
                       wmma::col_major> a0, a1;
        wmma::load_matrix_sync(a0, fL + wid * 16, LLD);
        wmma::load_matrix_sync(a1, fL + 8 * LLD + wid * 16, LLD);
        #pragma unroll
        for (int t = 0; t < a0.num_elements; t++) {
            a0.x[t] = wmma::__float_to_tf32(a0.x[t]);
            a1.x[t] = wmma::__float_to_tf32(a1.x[t]);
        }

        #pragma unroll
        for (int j = 0; j < 4; j++) {
            // B (8x16, row_major): (k,n) at fR[k*RLD + wid*16 + 16j + n]
            wmma::fragment<wmma::matrix_b, 16, 16, 8, wmma::precision::tf32,
                           wmma::row_major> b0, b1;
            wmma::load_matrix_sync(b0, fR + wid * 16 + 16 * j, RLD);
            wmma::load_matrix_sync(b1, fR + 8 * RLD + wid * 16 + 16 * j, RLD);
            #pragma unroll
            for (int t = 0; t < b0.num_elements; t++) {
                b0.x[t] = wmma::__float_to_tf32(b0.x[t]);
                b1.x[t] = wmma::__float_to_tf32(b1.x[t]);
            }
            wmma::mma_sync(acc[j], a0, b0, acc[j]);
            wmma::mma_sync(acc[j], a1, b1, acc[j]);
        }
    }

    // Scratch overlays the fp32 stages, which other warps were MMA-reading:
    // must sync before overwriting.
    __syncthreads();

    float* scr = (float*)(sm + SCR) + wid * 16 * SLD;
    #pragma unroll
    for (int j = 0; j < 4; j++)
        wmma::store_matrix_sync(scr + 16 * j, acc[j], SLD, wmma::mem_row_major);
    __syncwarp();

    // out[d][wg] = D[i][wg-d]/64; scratch col = i + 48 - d
    {
        const int i    = lid & 15;
        const int dpar = lid >> 4;
        const int wg   = h0 + wid * 16 + i;
        float* ob = out + ((size_t)b * DDn * HH + h) * WW + wg;
        #pragma unroll
        for (int dd = 0; dd < 24; dd++) {
            const int d = 2 * dd + dpar;
            ob[(size_t)d * HW] = scr[i * SLD + (i + 48 - d)] * 0.015625f;
        }
    }
}

extern "C" void kernel_launch(void* const* d_in, const int* in_sizes, int n_in,
                              void* d_out, int out_size)
{
    cudaFuncSetAttribute(corvol_tf32, cudaFuncAttributeMaxDynamicSharedMemorySize, SMEM_SZ);
    corvol_tf32<<<8 * HH * 2, NT, SMEM_SZ>>>((const float*)d_in[0],
                                             (const float*)d_in[1],
                                             (float*)d_out);
}